// round 1
// baseline (speedup 1.0000x reference)
#include <cuda_runtime.h>
#include <cuda_bf16.h>
#include <cstdint>

// Problem constants
#define BB 32768
#define II 512
#define HH 512
#define KK 1024   // concat(x, h) inner dim

// Tiling
#define TM 128
#define TN 64
#define TK 16
#define NTHREADS 256

// Fused 3-gate LSTM (forget gate is dead code in the reference):
//   i = sigmoid(x@Wxi + bxi + h@Whi)
//   c_next = i * tanh(x@Wxc + bxc + h@Whc)
//   o = sigmoid(x@Wxo + bxo + h@Who)
//   h_next = o * tanh(c_next)
__global__ __launch_bounds__(NTHREADS)
void lstm_fused_kernel(
    const float* __restrict__ x,   // [B, I]
    const float* __restrict__ h,   // [B, H]
    const float* __restrict__ Wxi, const float* __restrict__ Whi, const float* __restrict__ bxi,
    const float* __restrict__ Wxc, const float* __restrict__ Whc, const float* __restrict__ bxc,
    const float* __restrict__ Wxo, const float* __restrict__ Who, const float* __restrict__ bxo,
    float* __restrict__ out_h,     // [B, H]
    float* __restrict__ out_c)     // [B, H]
{
    __shared__ float As[TK][TM];          // A tile, stored k-major for m-contiguous reads
    __shared__ float Bs[3][TK][TN];       // B tiles for gates i, c, o

    const int m0 = blockIdx.y * TM;
    const int n0 = blockIdx.x * TN;

    const int t  = threadIdx.x;
    const int tx = t & 15;        // 0..15 -> n direction (4 cols each)
    const int ty = t >> 4;        // 0..15 -> m direction (8 rows each)
    const int row0 = ty * 8;
    const int col0 = tx * 4;

    float acc[3][8][4];
    #pragma unroll
    for (int g = 0; g < 3; ++g)
        #pragma unroll
        for (int i = 0; i < 8; ++i)
            #pragma unroll
            for (int j = 0; j < 4; ++j)
                acc[g][i][j] = 0.0f;

    // A-load thread mapping: m = t&127, kq = t>>7 (2 groups), 2 iterations of float4
    const int a_m  = t & 127;
    const int a_kq = t >> 7;          // 0..1
    // B-load thread mapping: one float4 per gate per iteration
    const int b_n4 = t & 15;          // float4 index in n (0..15)
    const int b_kk = t >> 4;          // 0..15

    const float* Wx[3] = {Wxi, Wxc, Wxo};
    const float* Wh[3] = {Whi, Whc, Who};

    for (int k0 = 0; k0 < KK; k0 += TK) {
        // ---- load A tile (128 x 16) ----
        #pragma unroll
        for (int it = 0; it < 2; ++it) {
            int kk = a_kq * 4 + it * 8;     // 0,4 or 8,12
            int k  = k0 + kk;
            const float* src = (k < II)
                ? (x + (size_t)(m0 + a_m) * II + k)
                : (h + (size_t)(m0 + a_m) * HH + (k - II));
            float4 v = *(const float4*)src;
            As[kk + 0][a_m] = v.x;
            As[kk + 1][a_m] = v.y;
            As[kk + 2][a_m] = v.z;
            As[kk + 3][a_m] = v.w;
        }
        // ---- load B tiles (3 x 16 x 64) ----
        {
            int k = k0 + b_kk;
            #pragma unroll
            for (int g = 0; g < 3; ++g) {
                const float* src = (k < II)
                    ? (Wx[g] + (size_t)k * HH + n0 + b_n4 * 4)
                    : (Wh[g] + (size_t)(k - II) * HH + n0 + b_n4 * 4);
                *(float4*)&Bs[g][b_kk][b_n4 * 4] = *(const float4*)src;
            }
        }
        __syncthreads();

        // ---- compute ----
        #pragma unroll
        for (int kk = 0; kk < TK; ++kk) {
            float a[8];
            *(float4*)&a[0] = *(const float4*)&As[kk][row0];
            *(float4*)&a[4] = *(const float4*)&As[kk][row0 + 4];
            float bi[4], bc[4], bo[4];
            *(float4*)bi = *(const float4*)&Bs[0][kk][col0];
            *(float4*)bc = *(const float4*)&Bs[1][kk][col0];
            *(float4*)bo = *(const float4*)&Bs[2][kk][col0];
            #pragma unroll
            for (int i = 0; i < 8; ++i) {
                #pragma unroll
                for (int j = 0; j < 4; ++j) {
                    acc[0][i][j] = fmaf(a[i], bi[j], acc[0][i][j]);
                    acc[1][i][j] = fmaf(a[i], bc[j], acc[1][i][j]);
                    acc[2][i][j] = fmaf(a[i], bo[j], acc[2][i][j]);
                }
            }
        }
        __syncthreads();
    }

    // ---- epilogue: bias + activations, write h_next / c_next ----
    float bi4[4], bc4[4], bo4[4];
    *(float4*)bi4 = *(const float4*)&bxi[n0 + col0];
    *(float4*)bc4 = *(const float4*)&bxc[n0 + col0];
    *(float4*)bo4 = *(const float4*)&bxo[n0 + col0];

    #pragma unroll
    for (int i = 0; i < 8; ++i) {
        int m = m0 + row0 + i;
        float hv[4], cv[4];
        #pragma unroll
        for (int j = 0; j < 4; ++j) {
            float ip = acc[0][i][j] + bi4[j];
            float cp = acc[1][i][j] + bc4[j];
            float op = acc[2][i][j] + bo4[j];
            float ig = 1.0f / (1.0f + expf(-ip));
            float og = 1.0f / (1.0f + expf(-op));
            float cn = ig * tanhf(cp);
            cv[j] = cn;
            hv[j] = og * tanhf(cn);
        }
        *(float4*)&out_h[(size_t)m * HH + n0 + col0] = *(float4*)hv;
        *(float4*)&out_c[(size_t)m * HH + n0 + col0] = *(float4*)cv;
    }
}

extern "C" void kernel_launch(void* const* d_in, const int* in_sizes, int n_in,
                              void* d_out, int out_size) {
    // metadata order:
    // 0:x 1:h 2:c_prev 3:Wxi 4:bxi 5:Whi 6:Wxf 7:bxf 8:Whf 9:Wxc 10:bxc 11:Whc 12:Wxo 13:bxo 14:Who
    const float* x   = (const float*)d_in[0];
    const float* h   = (const float*)d_in[1];
    const float* Wxi = (const float*)d_in[3];
    const float* bxi = (const float*)d_in[4];
    const float* Whi = (const float*)d_in[5];
    const float* Wxc = (const float*)d_in[9];
    const float* bxc = (const float*)d_in[10];
    const float* Whc = (const float*)d_in[11];
    const float* Wxo = (const float*)d_in[12];
    const float* bxo = (const float*)d_in[13];
    const float* Who = (const float*)d_in[14];

    float* out   = (float*)d_out;
    float* out_h = out;                       // first B*H: h_next
    float* out_c = out + (size_t)BB * HH;     // second B*H: c_next

    dim3 grid(HH / TN, BB / TM);              // (8, 256)
    dim3 block(NTHREADS);
    lstm_fused_kernel<<<grid, block>>>(x, h,
                                       Wxi, Whi, bxi,
                                       Wxc, Whc, bxc,
                                       Wxo, Who, bxo,
                                       out_h, out_c);
}

// round 3
// speedup vs baseline: 2.3645x; 2.3645x over previous
#include <cuda_runtime.h>
#include <cuda_bf16.h>
#include <cstdint>

// ---------------- problem constants ----------------
#define M_SZ 32768
#define H_SZ 512
#define N3   1536          // 3 gates * 512 (i, c, o)
#define K_SZ 1024          // concat(x,h)
#define NKC  48            // K' = 3072 bf16 / BK=64

#define SWX(x) ((x) ^ ((((x) >> 3)) & 0x70))

// ---------------- device scratch ----------------
__device__ __nv_bfloat16 g_Ah[(size_t)M_SZ * K_SZ];   // 64MB
__device__ __nv_bfloat16 g_Al[(size_t)M_SZ * K_SZ];   // 64MB
__device__ __nv_bfloat16 g_Bh[(size_t)N3 * K_SZ];     // 3MB  (W^T, n-major rows, k contiguous)
__device__ __nv_bfloat16 g_Bl[(size_t)N3 * K_SZ];     // 3MB
__device__ float         g_acc[(size_t)M_SZ * N3];    // 192MB pre-activations

// ---------------- helpers ----------------
__device__ __forceinline__ uint32_t smem_u32(const void* p) {
    uint32_t a;
    asm("{ .reg .u64 t; cvta.to.shared.u64 t, %1; cvt.u32.u64 %0, t; }" : "=r"(a) : "l"(p));
    return a;
}
__device__ __forceinline__ void cpa16(uint32_t d, const void* s) {
    asm volatile("cp.async.cg.shared.global [%0], [%1], 16;" :: "r"(d), "l"(s));
}
__device__ __forceinline__ void ldmx4(uint32_t* r, uint32_t a) {
    asm volatile("ldmatrix.sync.aligned.m8n8.x4.shared.b16 {%0,%1,%2,%3}, [%4];"
        : "=r"(r[0]), "=r"(r[1]), "=r"(r[2]), "=r"(r[3]) : "r"(a));
}
__device__ __forceinline__ void mma16816(float* c, const uint32_t* a, uint32_t b0, uint32_t b1) {
    asm volatile("mma.sync.aligned.m16n8k16.row.col.f32.bf16.bf16.f32 "
        "{%0,%1,%2,%3}, {%4,%5,%6,%7}, {%8,%9}, {%0,%1,%2,%3};"
        : "+f"(c[0]), "+f"(c[1]), "+f"(c[2]), "+f"(c[3])
        : "r"(a[0]), "r"(a[1]), "r"(a[2]), "r"(a[3]), "r"(b0), "r"(b1));
}

// ---------------- prep A: fp32 -> bf16 hi/lo split ----------------
__global__ __launch_bounds__(256)
void prep_a(const float* __restrict__ x, const float* __restrict__ h) {
    int gid = blockIdx.x * 256 + threadIdx.x;      // 8.4M threads, 4 floats each
    int m = gid >> 8;
    int k4 = (gid & 255) << 2;
    const float* src = (k4 < 512) ? (x + (size_t)m * 512 + k4)
                                  : (h + (size_t)m * 512 + (k4 - 512));
    float4 v = *(const float4*)src;
    float vv[4] = {v.x, v.y, v.z, v.w};
    __nv_bfloat16 hi[4], lo[4];
    #pragma unroll
    for (int i = 0; i < 4; ++i) {
        hi[i] = __float2bfloat16(vv[i]);
        lo[i] = __float2bfloat16(vv[i] - __bfloat162float(hi[i]));
    }
    size_t o = ((size_t)m << 10) + k4;
    *(uint2*)(g_Ah + o) = *(uint2*)hi;
    *(uint2*)(g_Al + o) = *(uint2*)lo;
}

// ---------------- prep B: transpose + hi/lo split ----------------
__global__ void prep_b(const float* __restrict__ Wxi, const float* __restrict__ Whi,
                       const float* __restrict__ Wxc, const float* __restrict__ Whc,
                       const float* __restrict__ Wxo, const float* __restrict__ Who) {
    __shared__ float tile[32][33];
    int n0 = blockIdx.x * 32;       // 0..1535
    int k0 = blockIdx.y * 32;       // 0..1023
    int g = n0 >> 9;
    int nc0 = n0 & 511;
    const float* Wx = (g == 0) ? Wxi : ((g == 1) ? Wxc : Wxo);
    const float* Wh = (g == 0) ? Whi : ((g == 1) ? Whc : Who);
    int tx = threadIdx.x, ty = threadIdx.y;   // 32 x 8
    #pragma unroll
    for (int r = ty; r < 32; r += 8) {
        int k = k0 + r;
        const float* W = (k < 512) ? (Wx + (size_t)k * 512) : (Wh + (size_t)(k - 512) * 512);
        tile[r][tx] = W[nc0 + tx];
    }
    __syncthreads();
    #pragma unroll
    for (int r = ty; r < 32; r += 8) {
        float v = tile[tx][r];                     // value W[k0+tx][n0+r]
        __nv_bfloat16 hi = __float2bfloat16(v);
        __nv_bfloat16 lo = __float2bfloat16(v - __bfloat162float(hi));
        size_t o = (size_t)(n0 + r) * 1024 + k0 + tx;
        g_Bh[o] = hi;
        g_Bl[o] = lo;
    }
}

// ---------------- main GEMM: D[M, N3] = sum over K'=3072 ----------------
// tiles: CTA 128x128x64, 8 warps (2m x 4n), warp 64x32, 3-stage cp.async pipeline
__global__ __launch_bounds__(256, 2)
void lstm_gemm() {
    extern __shared__ char dsm[];
    const uint32_t s0 = (smem_u32(dsm) + 1023) & ~1023u;

    const int tid = threadIdx.x;
    const int lane = tid & 31;
    const int wid = tid >> 5;
    const int wm = wid >> 2;       // 0..1 (m offset 64*wm)
    const int wn = wid & 3;        // 0..3 (n offset 32*wn)
    const int m0 = blockIdx.y << 7;
    const int n0 = blockIdx.x << 7;

    // loader: row r (0..127), half cb (0 or 64 bytes) -> 4 x 16B cp.async per matrix
    const int lr = tid >> 1;
    const int lcb = (tid & 1) << 6;
    const int loff = (lr << 7) + lcb;
    const uint32_t lpat = (uint32_t)((loff >> 3) & 0x70);

    // per-warp swizzled row-base offsets for ldmatrix (loop-invariant)
    uint32_t a_off[4], b_off[2];
    #pragma unroll
    for (int mt = 0; mt < 4; ++mt) {
        int ro = (((wm << 6) + (mt << 4) + (lane & 15)) << 7) + ((lane >> 4) << 4);
        a_off[mt] = (uint32_t)ro ^ (uint32_t)((ro >> 3) & 0x70);
    }
    #pragma unroll
    for (int ng = 0; ng < 2; ++ng) {
        int rr = (wn << 5) + (ng << 4) + (lane & 7) + (((lane >> 4) & 1) << 3);
        int ro = (rr << 7) + (((lane >> 3) & 1) << 4);
        b_off[ng] = (uint32_t)ro ^ (uint32_t)((ro >> 3) & 0x70);
    }

    float c[4][4][4];
    #pragma unroll
    for (int a = 0; a < 4; ++a)
        #pragma unroll
        for (int b = 0; b < 4; ++b)
            #pragma unroll
            for (int d = 0; d < 4; ++d) c[a][b][d] = 0.0f;

    // stage loader
    auto load_stage = [&](int s, int kc) {
        int seg = kc >> 4;
        int kk = (kc & 15) << 6;   // bf16 col within [0,1024)
        const __nv_bfloat16* A = (seg < 2) ? g_Ah : g_Al;
        const __nv_bfloat16* B = (seg == 1) ? g_Bl : g_Bh;
        const char* as = (const char*)(A + (((size_t)(m0 + lr)) << 10) + kk) + lcb;
        const char* bs = (const char*)(B + (((size_t)(n0 + lr)) << 10) + kk) + lcb;
        uint32_t sa = s0 + (uint32_t)s * 32768u;
        #pragma unroll
        for (int i = 0; i < 4; ++i) {
            uint32_t sw = (uint32_t)(loff + 16 * i) ^ lpat;
            cpa16(sa + sw, as + 16 * i);
            cpa16(sa + 16384u + sw, bs + 16 * i);
        }
    };

    load_stage(0, 0);
    asm volatile("cp.async.commit_group;" ::: "memory");
    load_stage(1, 1);
    asm volatile("cp.async.commit_group;" ::: "memory");

    for (int kc = 0; kc < NKC; ++kc) {
        asm volatile("cp.async.wait_group 1;" ::: "memory");
        __syncthreads();
        if (kc + 2 < NKC) load_stage((kc + 2) % 3, kc + 2);
        asm volatile("cp.async.commit_group;" ::: "memory");

        const uint32_t sA = s0 + (uint32_t)(kc % 3) * 32768u;
        const uint32_t sB = sA + 16384u;

        #pragma unroll
        for (int ks = 0; ks < 4; ++ks) {
            uint32_t af[4][4], bf[2][4];
            #pragma unroll
            for (int mt = 0; mt < 4; ++mt)
                ldmx4(af[mt], sA + (a_off[mt] ^ (uint32_t)(ks << 5)));
            #pragma unroll
            for (int ng = 0; ng < 2; ++ng)
                ldmx4(bf[ng], sB + (b_off[ng] ^ (uint32_t)(ks << 5)));
            #pragma unroll
            for (int mt = 0; mt < 4; ++mt)
                #pragma unroll
                for (int nt = 0; nt < 4; ++nt) {
                    const uint32_t* bp = &bf[nt >> 1][(nt & 1) * 2];
                    mma16816(c[mt][nt], af[mt], bp[0], bp[1]);
                }
        }
    }

    // epilogue: write fp32 pre-activations to scratch
    float* outp = g_acc + (size_t)(m0 + (wm << 6) + (lane >> 2)) * N3
                + n0 + (wn << 5) + ((lane & 3) << 1);
    #pragma unroll
    for (int mt = 0; mt < 4; ++mt) {
        #pragma unroll
        for (int nt = 0; nt < 4; ++nt) {
            float2 v0 = make_float2(c[mt][nt][0], c[mt][nt][1]);
            float2 v1 = make_float2(c[mt][nt][2], c[mt][nt][3]);
            *(float2*)(outp + (size_t)(mt * 16) * N3 + nt * 8)     = v0;
            *(float2*)(outp + (size_t)(mt * 16 + 8) * N3 + nt * 8) = v1;
        }
    }
}

// ---------------- final epilogue: bias + activations ----------------
__global__ __launch_bounds__(256)
void lstm_epi(const float* __restrict__ bxi, const float* __restrict__ bxc,
              const float* __restrict__ bxo,
              float* __restrict__ outh, float* __restrict__ outc) {
    int gid = blockIdx.x * 256 + threadIdx.x;   // 4 cols each
    int m = gid >> 7;
    int j4 = (gid & 127) << 2;
    const float* p = g_acc + (size_t)m * N3 + j4;
    float4 ai = *(const float4*)(p);
    float4 ac = *(const float4*)(p + 512);
    float4 ao = *(const float4*)(p + 1024);
    float4 bi = *(const float4*)(bxi + j4);
    float4 bc = *(const float4*)(bxc + j4);
    float4 bo = *(const float4*)(bxo + j4);

    float iv[4] = {ai.x + bi.x, ai.y + bi.y, ai.z + bi.z, ai.w + bi.w};
    float cv[4] = {ac.x + bc.x, ac.y + bc.y, ac.z + bc.z, ac.w + bc.w};
    float ov[4] = {ao.x + bo.x, ao.y + bo.y, ao.z + bo.z, ao.w + bo.w};

    float hres[4], cres[4];
    #pragma unroll
    for (int u = 0; u < 4; ++u) {
        float ig = 1.0f / (1.0f + __expf(-iv[u]));
        float og = 1.0f / (1.0f + __expf(-ov[u]));
        float tc = 1.0f - 2.0f / (__expf(2.0f * cv[u]) + 1.0f);
        float cn = ig * tc;
        float tn = 1.0f - 2.0f / (__expf(2.0f * cn) + 1.0f);
        cres[u] = cn;
        hres[u] = og * tn;
    }
    size_t o = (size_t)m * 512 + j4;
    *(float4*)(outh + o) = *(float4*)hres;
    *(float4*)(outc + o) = *(float4*)cres;
}

// ---------------- launcher ----------------
extern "C" void kernel_launch(void* const* d_in, const int* in_sizes, int n_in,
                              void* d_out, int out_size) {
    // 0:x 1:h 2:c_prev 3:Wxi 4:bxi 5:Whi 6:Wxf 7:bxf 8:Whf 9:Wxc 10:bxc 11:Whc 12:Wxo 13:bxo 14:Who
    const float* x   = (const float*)d_in[0];
    const float* h   = (const float*)d_in[1];
    const float* Wxi = (const float*)d_in[3];
    const float* bxi = (const float*)d_in[4];
    const float* Whi = (const float*)d_in[5];
    const float* Wxc = (const float*)d_in[9];
    const float* bxc = (const float*)d_in[10];
    const float* Whc = (const float*)d_in[11];
    const float* Wxo = (const float*)d_in[12];
    const float* bxo = (const float*)d_in[13];
    const float* Who = (const float*)d_in[14];

    float* outh = (float*)d_out;
    float* outc = outh + (size_t)M_SZ * H_SZ;

    static bool attr_set = false;
    cudaFuncSetAttribute(lstm_gemm, cudaFuncAttributeMaxDynamicSharedMemorySize, 3 * 32768 + 1024);
    (void)attr_set;

    prep_a<<<M_SZ * 256 / 256 / 4 * 4, 256>>>(x, h);      // 32768 blocks
    prep_b<<<dim3(48, 32), dim3(32, 8)>>>(Wxi, Whi, Wxc, Whc, Wxo, Who);
    lstm_gemm<<<dim3(12, 256), 256, 3 * 32768 + 1024>>>();
    lstm_epi<<<M_SZ * 128 / 256, 256>>>(bxi, bxc, bxo, outh, outc);
}

// round 4
// speedup vs baseline: 2.9413x; 1.2439x over previous
#include <cuda_runtime.h>
#include <cuda_bf16.h>
#include <cstdint>

// ---------------- problem constants ----------------
#define M_SZ 32768
#define H_SZ 512
#define K_SZ 1024          // concat(x,h)
#define NKC  48            // K' = 3072 bf16 / BK=64 (3 split products x 16 chunks)

// ---------------- device scratch ----------------
__device__ __nv_bfloat16 g_Ah[(size_t)M_SZ * K_SZ];   // 64MB
__device__ __nv_bfloat16 g_Al[(size_t)M_SZ * K_SZ];   // 64MB
__device__ __nv_bfloat16 g_Bh[(size_t)3 * H_SZ * K_SZ]; // 3MB (W^T: [gate*512+n][k])
__device__ __nv_bfloat16 g_Bl[(size_t)3 * H_SZ * K_SZ]; // 3MB

// ---------------- helpers ----------------
__device__ __forceinline__ uint32_t smem_u32(const void* p) {
    uint32_t a;
    asm("{ .reg .u64 t; cvta.to.shared.u64 t, %1; cvt.u32.u64 %0, t; }" : "=r"(a) : "l"(p));
    return a;
}
__device__ __forceinline__ void cpa16(uint32_t d, const void* s) {
    asm volatile("cp.async.cg.shared.global [%0], [%1], 16;" :: "r"(d), "l"(s));
}
__device__ __forceinline__ void ldmx4(uint32_t* r, uint32_t a) {
    asm volatile("ldmatrix.sync.aligned.m8n8.x4.shared.b16 {%0,%1,%2,%3}, [%4];"
        : "=r"(r[0]), "=r"(r[1]), "=r"(r[2]), "=r"(r[3]) : "r"(a));
}
__device__ __forceinline__ void mma16816(float* c, const uint32_t* a, uint32_t b0, uint32_t b1) {
    asm volatile("mma.sync.aligned.m16n8k16.row.col.f32.bf16.bf16.f32 "
        "{%0,%1,%2,%3}, {%4,%5,%6,%7}, {%8,%9}, {%0,%1,%2,%3};"
        : "+f"(c[0]), "+f"(c[1]), "+f"(c[2]), "+f"(c[3])
        : "r"(a[0]), "r"(a[1]), "r"(a[2]), "r"(a[3]), "r"(b0), "r"(b1));
}

// ---------------- prep A: fp32 -> bf16 hi/lo split ----------------
__global__ __launch_bounds__(256)
void prep_a(const float* __restrict__ x, const float* __restrict__ h) {
    int gid = blockIdx.x * 256 + threadIdx.x;
    int m = gid >> 8;
    int k4 = (gid & 255) << 2;
    const float* src = (k4 < 512) ? (x + (size_t)m * 512 + k4)
                                  : (h + (size_t)m * 512 + (k4 - 512));
    float4 v = *(const float4*)src;
    float vv[4] = {v.x, v.y, v.z, v.w};
    __nv_bfloat16 hi[4], lo[4];
    #pragma unroll
    for (int i = 0; i < 4; ++i) {
        hi[i] = __float2bfloat16(vv[i]);
        lo[i] = __float2bfloat16(vv[i] - __bfloat162float(hi[i]));
    }
    size_t o = ((size_t)m << 10) + k4;
    *(uint2*)(g_Ah + o) = *(uint2*)hi;
    *(uint2*)(g_Al + o) = *(uint2*)lo;
}

// ---------------- prep B: transpose + hi/lo split ----------------
__global__ void prep_b(const float* __restrict__ Wxi, const float* __restrict__ Whi,
                       const float* __restrict__ Wxc, const float* __restrict__ Whc,
                       const float* __restrict__ Wxo, const float* __restrict__ Who) {
    __shared__ float tile[32][33];
    int n0 = blockIdx.x * 32;       // 0..1535
    int k0 = blockIdx.y * 32;       // 0..1023
    int g = n0 >> 9;
    int nc0 = n0 & 511;
    const float* Wx = (g == 0) ? Wxi : ((g == 1) ? Wxc : Wxo);
    const float* Wh = (g == 0) ? Whi : ((g == 1) ? Whc : Who);
    int tx = threadIdx.x, ty = threadIdx.y;   // 32 x 8
    #pragma unroll
    for (int r = ty; r < 32; r += 8) {
        int k = k0 + r;
        const float* W = (k < 512) ? (Wx + (size_t)k * 512) : (Wh + (size_t)(k - 512) * 512);
        tile[r][tx] = W[nc0 + tx];
    }
    __syncthreads();
    #pragma unroll
    for (int r = ty; r < 32; r += 8) {
        float v = tile[tx][r];                     // W[k0+tx][n0+r]
        __nv_bfloat16 hi = __float2bfloat16(v);
        __nv_bfloat16 lo = __float2bfloat16(v - __bfloat162float(hi));
        size_t o = (size_t)(n0 + r) * 1024 + k0 + tx;
        g_Bh[o] = hi;
        g_Bl[o] = lo;
    }
}

// ---------------- fused GEMM + epilogue ----------------
// CTA: 128m x 128n x 3 gates. 512 threads = 16 warps (4m x 4n), warp 32x32/gate.
// smem stage = A(16KB) + B(3 x 16KB) = 64KB; 3 stages = 192KB. 1 CTA/SM.
__global__ __launch_bounds__(512, 1)
void lstm_gemm(const float* __restrict__ bxi, const float* __restrict__ bxc,
               const float* __restrict__ bxo,
               float* __restrict__ outh, float* __restrict__ outc) {
    extern __shared__ char dsm[];
    const uint32_t s0 = (smem_u32(dsm) + 1023) & ~1023u;

    const int tid  = threadIdx.x;
    const int lane = tid & 31;
    const int wid  = tid >> 5;
    const int wm   = wid >> 2;       // 0..3 -> m offset 32*wm
    const int wn   = wid & 3;        // 0..3 -> n offset 32*wn
    const int m0   = blockIdx.y << 7;
    const int n0   = blockIdx.x << 7;

    // loop-invariant swizzled ldmatrix offsets
    uint32_t a_off[2], b_off[2];
    #pragma unroll
    for (int mt = 0; mt < 2; ++mt) {
        int row = (wm << 5) + (mt << 4) + (lane & 15);
        int ro  = (row << 7) + ((lane >> 4) << 4);
        a_off[mt] = (uint32_t)ro ^ (uint32_t)((ro >> 3) & 0x70);
    }
    #pragma unroll
    for (int ng = 0; ng < 2; ++ng) {
        int rr = (wn << 5) + (ng << 4) + (lane & 7) + (((lane >> 4) & 1) << 3);
        int ro = (rr << 7) + (((lane >> 3) & 1) << 4);
        b_off[ng] = (uint32_t)ro ^ (uint32_t)((ro >> 3) & 0x70);
    }

    float c[3][2][4][4];
    #pragma unroll
    for (int g = 0; g < 3; ++g)
        #pragma unroll
        for (int mt = 0; mt < 2; ++mt)
            #pragma unroll
            for (int nt = 0; nt < 4; ++nt)
                #pragma unroll
                for (int e = 0; e < 4; ++e) c[g][mt][nt][e] = 0.0f;

    // stage loader: 4096 x 16B chunks (A:1024, B:3072), 8 per thread
    auto load_stage = [&](int s, int kc) {
        const int seg = kc >> 4;
        const int kb  = (kc & 15) << 7;   // byte offset within 2KB k-row
        const char* Abase = (const char*)((seg < 2) ? g_Ah : g_Al);
        const char* Bbase = (const char*)((seg == 1) ? g_Bl : g_Bh);
        const uint32_t sa = s0 + (uint32_t)s * 65536u;
        #pragma unroll
        for (int i = 0; i < 8; ++i) {
            int gid = tid + 512 * i;
            if (gid < 1024) {
                int arow = gid >> 3, grp = gid & 7;
                int ob = (arow << 7) + (grp << 4);
                cpa16(sa + ((uint32_t)ob ^ (uint32_t)((ob >> 3) & 0x70)),
                      Abase + (((size_t)(m0 + arow)) << 11) + kb + (grp << 4));
            } else {
                int t = gid - 1024;
                int g = t >> 10, n = (t >> 3) & 127, grp = t & 7;
                int ob = (n << 7) + (grp << 4);
                cpa16(sa + 16384u + ((uint32_t)g << 14)
                         + ((uint32_t)ob ^ (uint32_t)((ob >> 3) & 0x70)),
                      Bbase + (((size_t)((g << 9) + n0 + n)) << 11) + kb + (grp << 4));
            }
        }
    };

    load_stage(0, 0);
    asm volatile("cp.async.commit_group;" ::: "memory");
    load_stage(1, 1);
    asm volatile("cp.async.commit_group;" ::: "memory");

    for (int kc = 0; kc < NKC; ++kc) {
        asm volatile("cp.async.wait_group 1;" ::: "memory");
        __syncthreads();
        if (kc + 2 < NKC) load_stage((kc + 2) % 3, kc + 2);
        asm volatile("cp.async.commit_group;" ::: "memory");

        const uint32_t sA = s0 + (uint32_t)(kc % 3) * 65536u;

        #pragma unroll
        for (int ks = 0; ks < 4; ++ks) {
            uint32_t af[2][4];
            ldmx4(af[0], sA + (a_off[0] ^ (uint32_t)(ks << 5)));
            ldmx4(af[1], sA + (a_off[1] ^ (uint32_t)(ks << 5)));
            #pragma unroll
            for (int g = 0; g < 3; ++g) {
                const uint32_t sB = sA + 16384u + ((uint32_t)g << 14);
                uint32_t bf[2][4];
                ldmx4(bf[0], sB + (b_off[0] ^ (uint32_t)(ks << 5)));
                ldmx4(bf[1], sB + (b_off[1] ^ (uint32_t)(ks << 5)));
                #pragma unroll
                for (int mt = 0; mt < 2; ++mt)
                    #pragma unroll
                    for (int nt = 0; nt < 4; ++nt) {
                        const uint32_t* bp = &bf[nt >> 1][(nt & 1) * 2];
                        mma16816(c[g][mt][nt], af[mt], bp[0], bp[1]);
                    }
            }
        }
    }

    // ---- fused epilogue on register fragments ----
    // frag layout (m16n8): {e0,e1}: row = lane>>2, cols 2*(lane&3)+{0,1}; {e2,e3}: row+8
    const int ncb = n0 + (wn << 5) + ((lane & 3) << 1);
    float2 bi2[4], bc2[4], bo2[4];
    #pragma unroll
    for (int nt = 0; nt < 4; ++nt) {
        bi2[nt] = *(const float2*)(bxi + ncb + nt * 8);
        bc2[nt] = *(const float2*)(bxc + ncb + nt * 8);
        bo2[nt] = *(const float2*)(bxo + ncb + nt * 8);
    }

    #pragma unroll
    for (int mt = 0; mt < 2; ++mt) {
        #pragma unroll
        for (int half = 0; half < 2; ++half) {
            int m = m0 + (wm << 5) + (mt << 4) + (lane >> 2) + half * 8;
            size_t ob = (size_t)m * 512;
            #pragma unroll
            for (int nt = 0; nt < 4; ++nt) {
                float hv[2], cv[2];
                #pragma unroll
                for (int e = 0; e < 2; ++e) {
                    int idx = half * 2 + e;
                    float ip = c[0][mt][nt][idx] + (e ? bi2[nt].y : bi2[nt].x);
                    float cp = c[1][mt][nt][idx] + (e ? bc2[nt].y : bc2[nt].x);
                    float op = c[2][mt][nt][idx] + (e ? bo2[nt].y : bo2[nt].x);
                    float ig = 1.0f / (1.0f + __expf(-ip));
                    float og = 1.0f / (1.0f + __expf(-op));
                    float tc = 1.0f - 2.0f / (__expf(2.0f * cp) + 1.0f);
                    float cn = ig * tc;
                    float tn = 1.0f - 2.0f / (__expf(2.0f * cn) + 1.0f);
                    cv[e] = cn;
                    hv[e] = og * tn;
                }
                *(float2*)(outh + ob + ncb + nt * 8) = *(float2*)hv;
                *(float2*)(outc + ob + ncb + nt * 8) = *(float2*)cv;
            }
        }
    }
}

// ---------------- launcher ----------------
extern "C" void kernel_launch(void* const* d_in, const int* in_sizes, int n_in,
                              void* d_out, int out_size) {
    // 0:x 1:h 2:c_prev 3:Wxi 4:bxi 5:Whi 6:Wxf 7:bxf 8:Whf 9:Wxc 10:bxc 11:Whc 12:Wxo 13:bxo 14:Who
    const float* x   = (const float*)d_in[0];
    const float* h   = (const float*)d_in[1];
    const float* Wxi = (const float*)d_in[3];
    const float* bxi = (const float*)d_in[4];
    const float* Whi = (const float*)d_in[5];
    const float* Wxc = (const float*)d_in[9];
    const float* bxc = (const float*)d_in[10];
    const float* Whc = (const float*)d_in[11];
    const float* Wxo = (const float*)d_in[12];
    const float* bxo = (const float*)d_in[13];
    const float* Who = (const float*)d_in[14];

    float* outh = (float*)d_out;
    float* outc = outh + (size_t)M_SZ * H_SZ;

    cudaFuncSetAttribute(lstm_gemm, cudaFuncAttributeMaxDynamicSharedMemorySize,
                         3 * 65536 + 1024);

    prep_a<<<32768, 256>>>(x, h);
    prep_b<<<dim3(48, 32), dim3(32, 8)>>>(Wxi, Whi, Wxc, Whc, Wxo, Who);
    lstm_gemm<<<dim3(4, 256), 512, 3 * 65536 + 1024>>>(bxi, bxc, bxo, outh, outc);
}